// round 3
// baseline (speedup 1.0000x reference)
#include <cuda_runtime.h>
#include <cuda_bf16.h>

#define BB 4
#define NN 10000
#define MM 10000
#define PP 128
#define KS 32
#define ZF 128

// ---------------- device scratch (static: no allocation) ----------------
__device__ float4 g_noisy4[BB * NN];      // (x,y,z, x^2+y^2+z^2)
__device__ float4 g_clean4[BB * MM];
__device__ float4 g_forigin[BB * PP];
__device__ float  g_zpart[BB * PP * ZF];  // Ws1[3:]^T z + bs1 per (b,p)
__device__ float4 g_fpts[BB * PP * KS];   // gathered noisy neighbors
__device__ float  g_estim[BB * PP * KS * 3];
__device__ float  g_partial[BB * PP];

__device__ __forceinline__ float finf() { return __int_as_float(0x7f800000); }

// ---------------- K0: pack point clouds as float4 with |r|^2 ----------------
__global__ void k0_pack(const float* __restrict__ noisy, const float* __restrict__ clean) {
    int i = blockIdx.x * blockDim.x + threadIdx.x;
    if (i < BB * NN) {
        float x = noisy[i * 3 + 0], y = noisy[i * 3 + 1], z = noisy[i * 3 + 2];
        g_noisy4[i] = make_float4(x, y, z, fmaf(x, x, fmaf(y, y, z * z)));
    }
    if (i < BB * MM) {
        float x = clean[i * 3 + 0], y = clean[i * 3 + 1], z = clean[i * 3 + 2];
        g_clean4[i] = make_float4(x, y, z, fmaf(x, x, fmaf(y, y, z * z)));
    }
}

// ---------------- K1: f_origin, feat(sampled), zpart ----------------
__global__ void k1_feat(const float* __restrict__ noisy, const int* __restrict__ sidx,
                        const float* __restrict__ Wf1, const float* __restrict__ bf1,
                        const float* __restrict__ Wf2, const float* __restrict__ bf2,
                        const float* __restrict__ Ws1, const float* __restrict__ bs1) {
    int bp = blockIdx.x;            // 0..511
    int b = bp >> 7, p = bp & 127;
    int tid = threadIdx.x;          // 128 threads
    __shared__ float xyz[3];
    __shared__ float h[64];
    __shared__ float z[128];

    if (tid == 0) {
        int si = sidx[p];
        const float* s = noisy + ((size_t)b * NN + si) * 3;
        xyz[0] = s[0]; xyz[1] = s[1]; xyz[2] = s[2];
        g_forigin[bp] = make_float4(s[0], s[1], s[2], 0.f);
    }
    __syncthreads();

    if (tid < 64) {
        float a = bf1[tid];
        a = fmaf(xyz[0], Wf1[0 * 64 + tid], a);
        a = fmaf(xyz[1], Wf1[1 * 64 + tid], a);
        a = fmaf(xyz[2], Wf1[2 * 64 + tid], a);
        h[tid] = fmaxf(a, 0.f);
    }
    __syncthreads();

    {
        float a = bf2[tid];
#pragma unroll 16
        for (int i = 0; i < 64; ++i) a = fmaf(h[i], Wf2[i * 128 + tid], a);
        z[tid] = a;                 // feat: no relu on second layer
    }
    __syncthreads();

    {
        float a = bs1[tid];
#pragma unroll 16
        for (int i = 0; i < 128; ++i) a = fmaf(z[i], Ws1[(3 + i) * 128 + tid], a);
        g_zpart[bp * ZF + tid] = a;
    }
}

// ---------------- K2: KNN1 top-32 via threshold binary search ----------------
__global__ __launch_bounds__(256) void k2_knn1() {
    int bp = blockIdx.x;            // one query per block
    int b = bp >> 7;
    int tid = threadIdx.x;
    __shared__ unsigned keys[NN];   // 40 KB
    __shared__ unsigned s_cnt;

    float4 q = g_forigin[bp];
    float m2x = -2.0f * q.x, m2y = -2.0f * q.y, m2z = -2.0f * q.z;
    for (int r = tid; r < NN; r += 256) {
        float4 v = g_noisy4[b * NN + r];
        float s = fmaf(v.x, m2x, fmaf(v.y, m2y, fmaf(v.z, m2z, v.w))); // d2 - |q|^2
        unsigned u = __float_as_uint(s);
        u ^= ((unsigned)((int)u >> 31)) | 0x80000000u;  // monotone float->uint
        keys[r] = u;
    }
    __syncthreads();

    unsigned lo = 0u, hi = 0xFFFFFFFFu;
    for (int it = 0; it < 34 && lo + 1u < hi; ++it) {
        unsigned mid = lo + ((hi - lo) >> 1);
        if (tid == 0) s_cnt = 0;
        __syncthreads();
        unsigned c = 0;
        for (int r = tid; r < NN; r += 256) c += (keys[r] <= mid);
        c = __reduce_add_sync(0xFFFFFFFFu, c);
        if ((tid & 31) == 0) atomicAdd(&s_cnt, c);
        __syncthreads();
        unsigned cnt = s_cnt;
        __syncthreads();
        if (cnt >= 32u) { hi = mid; if (cnt == 32u) break; }
        else lo = mid;
    }
    unsigned T = hi;   // count(keys <= T) >= 32 (== 32 for distinct values)

    if (tid == 0) s_cnt = 0;
    __syncthreads();
    for (int r = tid; r < NN; r += 256) {
        if (keys[r] <= T) {
            unsigned pos = atomicAdd(&s_cnt, 1u);
            if (pos < 32u) g_fpts[bp * KS + pos] = g_noisy4[b * NN + r];
        }
    }
}

// ---------------- K3: score MLP, double-buffered weight loads ----------------
__global__ __launch_bounds__(128) void k3_mlp(const float* __restrict__ Ws1,
                                              const float* __restrict__ Ws2,
                                              const float* __restrict__ bs2,
                                              const float* __restrict__ Ws3,
                                              const float* __restrict__ bs3) {
    int bp = blockIdx.x;
    int tid = threadIdx.x;          // 128 threads
    __shared__ float xs[KS][4];
    __shared__ float h1s[KS * 129]; // padded rows: conflict-free
    __shared__ float h2s[KS * 68];

    float4 o4 = g_forigin[bp];
    if (tid < 32) {
        float4 f = g_fpts[bp * KS + tid];
        xs[tid][0] = f.x - o4.x;
        xs[tid][1] = f.y - o4.y;
        xs[tid][2] = f.z - o4.z;
    }
    float zp = g_zpart[bp * ZF + tid];
    float w0 = Ws1[0 * 128 + tid], w1 = Ws1[1 * 128 + tid], w2 = Ws1[2 * 128 + tid];
    __syncthreads();

    // layer 1: h1 = relu(x0*w0 + x1*w1 + x2*w2 + zpart)
#pragma unroll
    for (int k = 0; k < KS; ++k) {
        float a = fmaf(xs[k][2], w2, fmaf(xs[k][1], w1, fmaf(xs[k][0], w0, zp)));
        h1s[k * 129 + tid] = fmaxf(a, 0.f);
    }
    __syncthreads();

    // layer 2: lane = k, warp = output-quarter; double-buffered weights
    {
        int k = tid & 31, oq = tid >> 5;
        float acc[16];
#pragma unroll
        for (int j = 0; j < 16; ++j) acc[j] = bs2[oq * 16 + j];
        const float* hrow = &h1s[k * 129];
        const float4* __restrict__ wbase = (const float4*)(Ws2) + oq * 4;

        float4 wa = wbase[0], wb = wbase[1], wc = wbase[2], wd = wbase[3];
#pragma unroll 4
        for (int i = 0; i < 127; ++i) {
            float4 na = wbase[(i + 1) * 16 + 0];
            float4 nb = wbase[(i + 1) * 16 + 1];
            float4 nc = wbase[(i + 1) * 16 + 2];
            float4 nd = wbase[(i + 1) * 16 + 3];
            float hv = hrow[i];
            acc[0]  = fmaf(hv, wa.x, acc[0]);  acc[1]  = fmaf(hv, wa.y, acc[1]);
            acc[2]  = fmaf(hv, wa.z, acc[2]);  acc[3]  = fmaf(hv, wa.w, acc[3]);
            acc[4]  = fmaf(hv, wb.x, acc[4]);  acc[5]  = fmaf(hv, wb.y, acc[5]);
            acc[6]  = fmaf(hv, wb.z, acc[6]);  acc[7]  = fmaf(hv, wb.w, acc[7]);
            acc[8]  = fmaf(hv, wc.x, acc[8]);  acc[9]  = fmaf(hv, wc.y, acc[9]);
            acc[10] = fmaf(hv, wc.z, acc[10]); acc[11] = fmaf(hv, wc.w, acc[11]);
            acc[12] = fmaf(hv, wd.x, acc[12]); acc[13] = fmaf(hv, wd.y, acc[13]);
            acc[14] = fmaf(hv, wd.z, acc[14]); acc[15] = fmaf(hv, wd.w, acc[15]);
            wa = na; wb = nb; wc = nc; wd = nd;
        }
        {
            float hv = hrow[127];
            acc[0]  = fmaf(hv, wa.x, acc[0]);  acc[1]  = fmaf(hv, wa.y, acc[1]);
            acc[2]  = fmaf(hv, wa.z, acc[2]);  acc[3]  = fmaf(hv, wa.w, acc[3]);
            acc[4]  = fmaf(hv, wb.x, acc[4]);  acc[5]  = fmaf(hv, wb.y, acc[5]);
            acc[6]  = fmaf(hv, wb.z, acc[6]);  acc[7]  = fmaf(hv, wb.w, acc[7]);
            acc[8]  = fmaf(hv, wc.x, acc[8]);  acc[9]  = fmaf(hv, wc.y, acc[9]);
            acc[10] = fmaf(hv, wc.z, acc[10]); acc[11] = fmaf(hv, wc.w, acc[11]);
            acc[12] = fmaf(hv, wd.x, acc[12]); acc[13] = fmaf(hv, wd.y, acc[13]);
            acc[14] = fmaf(hv, wd.z, acc[14]); acc[15] = fmaf(hv, wd.w, acc[15]);
        }
#pragma unroll
        for (int j = 0; j < 16; ++j) h2s[k * 68 + oq * 16 + j] = fmaxf(acc[j], 0.f);
    }
    __syncthreads();

    // layer 3: 96 threads, (k,d)
    if (tid < 96) {
        int k = tid / 3, d = tid % 3;
        float a = bs3[d];
#pragma unroll 16
        for (int i = 0; i < 64; ++i) a = fmaf(h2s[k * 68 + i], Ws3[i * 3 + d], a);
        g_estim[(bp * KS + k) * 3 + d] = a;
    }
}

// insertion into sorted 4-element top list
#define INS4(s, id, s0, s1, s2, s3, i0, i1, i2, i3)             \
    if ((s) < (s3)) {                                           \
        if ((s) < (s2)) {                                       \
            (s3) = (s2); (i3) = (i2);                           \
            if ((s) < (s1)) {                                   \
                (s2) = (s1); (i2) = (i1);                       \
                if ((s) < (s0)) { (s1) = (s0); (i1) = (i0); (s0) = (s); (i0) = (id); } \
                else { (s1) = (s); (i1) = (id); }               \
            } else { (s2) = (s); (i2) = (id); }                 \
        } else { (s3) = (s); (i3) = (id); }                     \
    }

// ---------------- K4: KNN2 top-4, 2 bp per block ----------------
struct RedScratch {
    float cs[2][8][32][4];
    int   ci[2][8][32][4];
};

__global__ __launch_bounds__(256) void k4_knn2() {
    int blk = blockIdx.x;                         // 256 blocks
    int b = blk >> 6, pp = blk & 63;
    int bpA = b * PP + pp;
    int bpB = b * PP + pp + 64;
    int tid = threadIdx.x, lane = tid & 31, w = tid >> 5;   // 8 warps

    __shared__ union SU {
        float4 buf[2048];                         // 32 KB tile
        RedScratch red;                           // 16 KB, reused after scan
    } sm;

    float4 fA = g_fpts[bpA * KS + lane];
    float4 fB = g_fpts[bpB * KS + lane];
    float aAx = -2.0f * fA.x, aAy = -2.0f * fA.y, aAz = -2.0f * fA.z;
    float aBx = -2.0f * fB.x, aBy = -2.0f * fB.y, aBz = -2.0f * fB.z;

    float A0 = finf(), A1 = finf(), A2 = finf(), A3 = finf();
    int   a0 = 0, a1 = 0, a2 = 0, a3 = 0;
    float B0 = finf(), B1 = finf(), B2 = finf(), B3 = finf();
    int   b0 = 0, b1 = 0, b2 = 0, b3 = 0;

    for (int t0 = 0; t0 < MM; t0 += 2048) {
        int n = min(2048, MM - t0);
        __syncthreads();
        for (int j = tid; j < n; j += 256) sm.buf[j] = g_clean4[b * MM + t0 + j];
        __syncthreads();
        int chunk = (n + 7) >> 3;
        int start = w * chunk;
        int end = min(start + chunk, n);
#pragma unroll 4
        for (int r = start; r < end; ++r) {
            float4 v = sm.buf[r];                 // broadcast LDS.128
            int id = t0 + r;
            float sA = fmaf(v.x, aAx, fmaf(v.y, aAy, fmaf(v.z, aAz, v.w)));
            float sB = fmaf(v.x, aBx, fmaf(v.y, aBy, fmaf(v.z, aBz, v.w)));
            INS4(sA, id, A0, A1, A2, A3, a0, a1, a2, a3);
            INS4(sB, id, B0, B1, B2, B3, b0, b1, b2, b3);
        }
    }
    __syncthreads();    // all warps done reading buf — safe to overlay
    sm.red.cs[0][w][lane][0] = A0; sm.red.cs[0][w][lane][1] = A1;
    sm.red.cs[0][w][lane][2] = A2; sm.red.cs[0][w][lane][3] = A3;
    sm.red.ci[0][w][lane][0] = a0; sm.red.ci[0][w][lane][1] = a1;
    sm.red.ci[0][w][lane][2] = a2; sm.red.ci[0][w][lane][3] = a3;
    sm.red.cs[1][w][lane][0] = B0; sm.red.cs[1][w][lane][1] = B1;
    sm.red.cs[1][w][lane][2] = B2; sm.red.cs[1][w][lane][3] = B3;
    sm.red.ci[1][w][lane][0] = b0; sm.red.ci[1][w][lane][1] = b1;
    sm.red.ci[1][w][lane][2] = b2; sm.red.ci[1][w][lane][3] = b3;
    __syncthreads();

    if (w < 2) {                                  // warp 0 -> query A, warp 1 -> query B
        int q = w;
        int bp = q ? bpB : bpA;
        float4 f = q ? fB : fA;
        float c0s = finf(), c1s = finf(), c2s = finf(), c3s = finf();
        int   j0 = 0, j1 = 0, j2 = 0, j3 = 0;
#pragma unroll
        for (int ww = 0; ww < 8; ++ww)
#pragma unroll
            for (int jj = 0; jj < 4; ++jj) {
                float s = sm.red.cs[q][ww][lane][jj];
                int id = sm.red.ci[q][ww][lane][jj];
                INS4(s, id, c0s, c1s, c2s, c3s, j0, j1, j2, j3);
            }
        float4 c0 = g_clean4[b * MM + j0];
        float4 c1 = g_clean4[b * MM + j1];
        float4 c2 = g_clean4[b * MM + j2];
        float4 c3 = g_clean4[b * MM + j3];
        float gx = (c0.x + c1.x + c2.x + c3.x) * 0.25f - f.x;
        float gy = (c0.y + c1.y + c2.y + c3.y) * 0.25f - f.y;
        float gz = (c0.z + c1.z + c2.z + c3.z) * 0.25f - f.z;
        const float* e = g_estim + (bp * KS + lane) * 3;
        float d0 = e[0] - gx, d1 = e[1] - gy, d2v = e[2] - gz;
        float err = fmaf(d0, d0, fmaf(d1, d1, d2v * d2v));
#pragma unroll
        for (int off = 16; off > 0; off >>= 1)
            err += __shfl_xor_sync(0xFFFFFFFFu, err, off);
        if (lane == 0) g_partial[bp] = err;
    }
}

// ---------------- K5: deterministic final reduce ----------------
__global__ void k5_reduce(float* __restrict__ out) {
    __shared__ float sm[512];
    int tid = threadIdx.x;
    sm[tid] = g_partial[tid];
    __syncthreads();
#pragma unroll
    for (int s = 256; s > 0; s >>= 1) {
        if (tid < s) sm[tid] += sm[tid + s];
        __syncthreads();
    }
    // loss = 0.5 * mean_{B*P*K}( sum_d (.)^2 / SIGMA ) = total * 0.5*100/16384
    if (tid == 0) out[0] = sm[0] * (50.0f / 16384.0f);
}

extern "C" void kernel_launch(void* const* d_in, const int* in_sizes, int n_in,
                              void* d_out, int out_size) {
    const float* noisy = (const float*)d_in[0];
    const float* clean = (const float*)d_in[1];
    const int*   sidx  = (const int*)d_in[2];
    const float* Wf1 = (const float*)d_in[3];
    const float* bf1 = (const float*)d_in[4];
    const float* Wf2 = (const float*)d_in[5];
    const float* bf2 = (const float*)d_in[6];
    const float* Ws1 = (const float*)d_in[7];
    const float* bs1 = (const float*)d_in[8];
    const float* Ws2 = (const float*)d_in[9];
    const float* bs2 = (const float*)d_in[10];
    const float* Ws3 = (const float*)d_in[11];
    const float* bs3 = (const float*)d_in[12];
    float* out = (float*)d_out;

    k0_pack<<<(BB * NN + 255) / 256, 256>>>(noisy, clean);
    k1_feat<<<BB * PP, 128>>>(noisy, sidx, Wf1, bf1, Wf2, bf2, Ws1, bs1);
    k2_knn1<<<BB * PP, 256>>>();
    k3_mlp<<<BB * PP, 128>>>(Ws1, Ws2, bs2, Ws3, bs3);
    k4_knn2<<<BB * PP / 2, 256>>>();
    k5_reduce<<<1, 512>>>(out);
}

// round 4
// speedup vs baseline: 1.0984x; 1.0984x over previous
#include <cuda_runtime.h>
#include <cuda_bf16.h>

#define BB 4
#define NN 10000
#define MM 10000
#define PP 128
#define KS 32
#define ZF 128

// ---------------- device scratch (static: no allocation) ----------------
__device__ float4 g_noisy4[BB * NN];      // (x,y,z, x^2+y^2+z^2)
__device__ float4 g_clean4[BB * MM];
__device__ float4 g_forigin[BB * PP];
__device__ float  g_zpart[BB * PP * ZF];  // Ws1[3:]^T z + bs1 per (b,p)
__device__ float4 g_fpts[BB * PP * KS];   // gathered noisy neighbors
__device__ float  g_estim[BB * PP * KS * 3];
__device__ float  g_partial[BB * PP];

__device__ __forceinline__ float finf() { return __int_as_float(0x7f800000); }

// ---------------- K0: pack point clouds as float4 with |r|^2 ----------------
__global__ void k0_pack(const float* __restrict__ noisy, const float* __restrict__ clean) {
    int i = blockIdx.x * blockDim.x + threadIdx.x;
    if (i < BB * NN) {
        float x = noisy[i * 3 + 0], y = noisy[i * 3 + 1], z = noisy[i * 3 + 2];
        g_noisy4[i] = make_float4(x, y, z, fmaf(x, x, fmaf(y, y, z * z)));
    }
    if (i < BB * MM) {
        float x = clean[i * 3 + 0], y = clean[i * 3 + 1], z = clean[i * 3 + 2];
        g_clean4[i] = make_float4(x, y, z, fmaf(x, x, fmaf(y, y, z * z)));
    }
}

// ---------------- K1: f_origin, feat(sampled), zpart ----------------
__global__ void k1_feat(const float* __restrict__ noisy, const int* __restrict__ sidx,
                        const float* __restrict__ Wf1, const float* __restrict__ bf1,
                        const float* __restrict__ Wf2, const float* __restrict__ bf2,
                        const float* __restrict__ Ws1, const float* __restrict__ bs1) {
    int bp = blockIdx.x;            // 0..511
    int b = bp >> 7, p = bp & 127;
    int tid = threadIdx.x;          // 128 threads
    __shared__ float xyz[3];
    __shared__ float h[64];
    __shared__ float z[128];

    if (tid == 0) {
        int si = sidx[p];
        const float* s = noisy + ((size_t)b * NN + si) * 3;
        xyz[0] = s[0]; xyz[1] = s[1]; xyz[2] = s[2];
        g_forigin[bp] = make_float4(s[0], s[1], s[2], 0.f);
    }
    __syncthreads();

    if (tid < 64) {
        float a = bf1[tid];
        a = fmaf(xyz[0], Wf1[0 * 64 + tid], a);
        a = fmaf(xyz[1], Wf1[1 * 64 + tid], a);
        a = fmaf(xyz[2], Wf1[2 * 64 + tid], a);
        h[tid] = fmaxf(a, 0.f);
    }
    __syncthreads();

    {
        float a = bf2[tid];
#pragma unroll 16
        for (int i = 0; i < 64; ++i) a = fmaf(h[i], Wf2[i * 128 + tid], a);
        z[tid] = a;                 // feat: no relu on second layer
    }
    __syncthreads();

    {
        float a = bs1[tid];
#pragma unroll 16
        for (int i = 0; i < 128; ++i) a = fmaf(z[i], Ws1[(3 + i) * 128 + tid], a);
        g_zpart[bp * ZF + tid] = a;
    }
}

// ---------------- K2: KNN1 top-32 via threshold binary search ----------------
__global__ __launch_bounds__(256) void k2_knn1() {
    int bp = blockIdx.x;            // one query per block
    int b = bp >> 7;
    int tid = threadIdx.x;
    __shared__ unsigned keys[NN];   // 40 KB
    __shared__ unsigned s_cnt;

    float4 q = g_forigin[bp];
    float m2x = -2.0f * q.x, m2y = -2.0f * q.y, m2z = -2.0f * q.z;
    for (int r = tid; r < NN; r += 256) {
        float4 v = g_noisy4[b * NN + r];
        float s = fmaf(v.x, m2x, fmaf(v.y, m2y, fmaf(v.z, m2z, v.w))); // d2 - |q|^2
        unsigned u = __float_as_uint(s);
        u ^= ((unsigned)((int)u >> 31)) | 0x80000000u;  // monotone float->uint
        keys[r] = u;
    }
    __syncthreads();

    unsigned lo = 0u, hi = 0xFFFFFFFFu;
    for (int it = 0; it < 34 && lo + 1u < hi; ++it) {
        unsigned mid = lo + ((hi - lo) >> 1);
        if (tid == 0) s_cnt = 0;
        __syncthreads();
        unsigned c = 0;
        for (int r = tid; r < NN; r += 256) c += (keys[r] <= mid);
        c = __reduce_add_sync(0xFFFFFFFFu, c);
        if ((tid & 31) == 0) atomicAdd(&s_cnt, c);
        __syncthreads();
        unsigned cnt = s_cnt;
        __syncthreads();
        if (cnt >= 32u) { hi = mid; if (cnt == 32u) break; }
        else lo = mid;
    }
    unsigned T = hi;   // count(keys <= T) >= 32 (== 32 for distinct values)

    if (tid == 0) s_cnt = 0;
    __syncthreads();
    for (int r = tid; r < NN; r += 256) {
        if (keys[r] <= T) {
            unsigned pos = atomicAdd(&s_cnt, 1u);
            if (pos < 32u) g_fpts[bp * KS + pos] = g_noisy4[b * NN + r];
        }
    }
}

// ---------------- K3: score MLP — ONE WARP PER (bp,k) ROW ----------------
// 16384 rows, 8 warps/block -> 2048 blocks, full occupancy.
__global__ __launch_bounds__(256) void k3_mlp(const float* __restrict__ Ws1,
                                              const float* __restrict__ Ws2,
                                              const float* __restrict__ bs2,
                                              const float* __restrict__ Ws3,
                                              const float* __restrict__ bs3) {
    __shared__ float hsh[8][128];
    int w = threadIdx.x >> 5, lane = threadIdx.x & 31;
    int row = blockIdx.x * 8 + w;        // 0..16383 == bp*KS + k
    int bp = row >> 5;

    float4 f = g_fpts[row];
    float4 o = g_forigin[bp];
    float x0 = f.x - o.x, x1 = f.y - o.y, x2 = f.z - o.z;

    // layer 1: lane computes features 4*lane .. 4*lane+3
    float4 zp = *(const float4*)(g_zpart + bp * ZF + lane * 4);
    float4 w0 = *(const float4*)(Ws1 + 0 * 128 + lane * 4);
    float4 w1 = *(const float4*)(Ws1 + 1 * 128 + lane * 4);
    float4 w2 = *(const float4*)(Ws1 + 2 * 128 + lane * 4);
    float4 h4;
    h4.x = fmaxf(fmaf(x2, w2.x, fmaf(x1, w1.x, fmaf(x0, w0.x, zp.x))), 0.f);
    h4.y = fmaxf(fmaf(x2, w2.y, fmaf(x1, w1.y, fmaf(x0, w0.y, zp.y))), 0.f);
    h4.z = fmaxf(fmaf(x2, w2.z, fmaf(x1, w1.z, fmaf(x0, w0.z, zp.z))), 0.f);
    h4.w = fmaxf(fmaf(x2, w2.w, fmaf(x1, w1.w, fmaf(x0, w0.w, zp.w))), 0.f);
    *(float4*)&hsh[w][lane * 4] = h4;
    __syncwarp();

    // layer 2: lane computes output columns 2*lane, 2*lane+1
    float acc0 = bs2[2 * lane], acc1 = bs2[2 * lane + 1];
    const float2* __restrict__ W2 = (const float2*)(Ws2) + lane;  // (i, 2*lane)
#pragma unroll 8
    for (int i = 0; i < 128; i += 4) {
        float4 hv = *(const float4*)&hsh[w][i];      // broadcast LDS.128
        float2 wv0 = W2[(i + 0) * 32];
        float2 wv1 = W2[(i + 1) * 32];
        float2 wv2 = W2[(i + 2) * 32];
        float2 wv3 = W2[(i + 3) * 32];
        acc0 = fmaf(hv.x, wv0.x, acc0); acc1 = fmaf(hv.x, wv0.y, acc1);
        acc0 = fmaf(hv.y, wv1.x, acc0); acc1 = fmaf(hv.y, wv1.y, acc1);
        acc0 = fmaf(hv.z, wv2.x, acc0); acc1 = fmaf(hv.z, wv2.y, acc1);
        acc0 = fmaf(hv.w, wv3.x, acc0); acc1 = fmaf(hv.w, wv3.y, acc1);
    }
    float h20 = fmaxf(acc0, 0.f), h21 = fmaxf(acc1, 0.f);

    // layer 3: lane contributes rows 2*lane, 2*lane+1 of Ws3; warp-reduce
    const float* __restrict__ w3 = Ws3 + 6 * lane;
    float p0 = fmaf(h20, w3[0], h21 * w3[3]);
    float p1 = fmaf(h20, w3[1], h21 * w3[4]);
    float p2 = fmaf(h20, w3[2], h21 * w3[5]);
#pragma unroll
    for (int off = 16; off > 0; off >>= 1) {
        p0 += __shfl_xor_sync(0xFFFFFFFFu, p0, off);
        p1 += __shfl_xor_sync(0xFFFFFFFFu, p1, off);
        p2 += __shfl_xor_sync(0xFFFFFFFFu, p2, off);
    }
    if (lane == 0) {
        g_estim[row * 3 + 0] = p0 + bs3[0];
        g_estim[row * 3 + 1] = p1 + bs3[1];
        g_estim[row * 3 + 2] = p2 + bs3[2];
    }
}

// insertion into sorted 4-element top list
#define INS4(s, id, s0, s1, s2, s3, i0, i1, i2, i3)             \
    if ((s) < (s3)) {                                           \
        if ((s) < (s2)) {                                       \
            (s3) = (s2); (i3) = (i2);                           \
            if ((s) < (s1)) {                                   \
                (s2) = (s1); (i2) = (i1);                       \
                if ((s) < (s0)) { (s1) = (s0); (i1) = (i0); (s0) = (s); (i0) = (id); } \
                else { (s1) = (s); (i1) = (id); }               \
            } else { (s2) = (s); (i2) = (id); }                 \
        } else { (s3) = (s); (i3) = (id); }                     \
    }

// ---------------- K4: KNN2 top-4, 1 bp per block, 16 warps ----------------
__global__ __launch_bounds__(512) void k4_knn2() {
    int bp = blockIdx.x;
    int b = bp >> 7;
    int tid = threadIdx.x, lane = tid & 31, w = tid >> 5;   // 16 warps

    __shared__ union SU {
        float4 buf[2048];                         // 32 KB tile
        struct { float cs[16][32][4]; int ci[16][32][4]; } red;
    } sm;

    float4 f = g_fpts[bp * KS + lane];            // lane = query k
    float m2x = -2.0f * f.x, m2y = -2.0f * f.y, m2z = -2.0f * f.z;
    float s0 = finf(), s1 = finf(), s2 = finf(), s3 = finf();
    int   i0 = 0, i1 = 0, i2 = 0, i3 = 0;

    for (int t0 = 0; t0 < MM; t0 += 2048) {
        int n = min(2048, MM - t0);
        __syncthreads();
        for (int j = tid; j < n; j += 512) sm.buf[j] = g_clean4[b * MM + t0 + j];
        __syncthreads();
        int chunk = (n + 15) >> 4;
        int start = w * chunk;
        int end = min(start + chunk, n);
#pragma unroll 4
        for (int r = start; r < end; ++r) {
            float4 v = sm.buf[r];                 // broadcast LDS.128
            float s = fmaf(v.x, m2x, fmaf(v.y, m2y, fmaf(v.z, m2z, v.w)));
            int id = t0 + r;
            INS4(s, id, s0, s1, s2, s3, i0, i1, i2, i3);
        }
    }
    __syncthreads();   // done reading buf — safe to overlay
    sm.red.cs[w][lane][0] = s0; sm.red.cs[w][lane][1] = s1;
    sm.red.cs[w][lane][2] = s2; sm.red.cs[w][lane][3] = s3;
    sm.red.ci[w][lane][0] = i0; sm.red.ci[w][lane][1] = i1;
    sm.red.ci[w][lane][2] = i2; sm.red.ci[w][lane][3] = i3;
    __syncthreads();

    if (w == 0) {
        float b0 = finf(), b1 = finf(), b2 = finf(), b3 = finf();
        int   j0 = 0, j1 = 0, j2 = 0, j3 = 0;
#pragma unroll
        for (int ww = 0; ww < 16; ++ww)
#pragma unroll
            for (int jj = 0; jj < 4; ++jj) {
                float s = sm.red.cs[ww][lane][jj];
                int id = sm.red.ci[ww][lane][jj];
                INS4(s, id, b0, b1, b2, b3, j0, j1, j2, j3);
            }
        float4 c0 = g_clean4[b * MM + j0];
        float4 c1 = g_clean4[b * MM + j1];
        float4 c2 = g_clean4[b * MM + j2];
        float4 c3 = g_clean4[b * MM + j3];
        float gx = (c0.x + c1.x + c2.x + c3.x) * 0.25f - f.x;
        float gy = (c0.y + c1.y + c2.y + c3.y) * 0.25f - f.y;
        float gz = (c0.z + c1.z + c2.z + c3.z) * 0.25f - f.z;
        const float* e = g_estim + (bp * KS + lane) * 3;
        float d0 = e[0] - gx, d1 = e[1] - gy, d2v = e[2] - gz;
        float err = fmaf(d0, d0, fmaf(d1, d1, d2v * d2v));
#pragma unroll
        for (int off = 16; off > 0; off >>= 1)
            err += __shfl_xor_sync(0xFFFFFFFFu, err, off);
        if (lane == 0) g_partial[bp] = err;
    }
}

// ---------------- K5: deterministic final reduce ----------------
__global__ void k5_reduce(float* __restrict__ out) {
    __shared__ float sm[512];
    int tid = threadIdx.x;
    sm[tid] = g_partial[tid];
    __syncthreads();
#pragma unroll
    for (int s = 256; s > 0; s >>= 1) {
        if (tid < s) sm[tid] += sm[tid + s];
        __syncthreads();
    }
    // loss = 0.5 * mean_{B*P*K}( sum_d (.)^2 / SIGMA ) = total * 0.5*100/16384
    if (tid == 0) out[0] = sm[0] * (50.0f / 16384.0f);
}

extern "C" void kernel_launch(void* const* d_in, const int* in_sizes, int n_in,
                              void* d_out, int out_size) {
    const float* noisy = (const float*)d_in[0];
    const float* clean = (const float*)d_in[1];
    const int*   sidx  = (const int*)d_in[2];
    const float* Wf1 = (const float*)d_in[3];
    const float* bf1 = (const float*)d_in[4];
    const float* Wf2 = (const float*)d_in[5];
    const float* bf2 = (const float*)d_in[6];
    const float* Ws1 = (const float*)d_in[7];
    const float* bs1 = (const float*)d_in[8];
    const float* Ws2 = (const float*)d_in[9];
    const float* bs2 = (const float*)d_in[10];
    const float* Ws3 = (const float*)d_in[11];
    const float* bs3 = (const float*)d_in[12];
    float* out = (float*)d_out;

    k0_pack<<<(BB * NN + 255) / 256, 256>>>(noisy, clean);
    k1_feat<<<BB * PP, 128>>>(noisy, sidx, Wf1, bf1, Wf2, bf2, Ws1, bs1);
    k2_knn1<<<BB * PP, 256>>>();
    k3_mlp<<<BB * PP * KS / 8, 256>>>(Ws1, Ws2, bs2, Ws3, bs3);
    k4_knn2<<<BB * PP, 512>>>();
    k5_reduce<<<1, 512>>>(out);
}

// round 5
// speedup vs baseline: 1.2293x; 1.1192x over previous
#include <cuda_runtime.h>
#include <cuda_bf16.h>

#define BB 4
#define NN 10000
#define MM 10000
#define PP 128
#define KS 32
#define ZF 128

// ---------------- device scratch (static: no allocation) ----------------
__device__ float4 g_noisy4[BB * NN];      // (x,y,z, x^2+y^2+z^2)
__device__ float4 g_clean4[BB * MM];
__device__ float4 g_forigin[BB * PP];
__device__ float  g_zpart[BB * PP * ZF];  // Ws1[3:]^T z + bs1 per (b,p)
__device__ float4 g_fpts[BB * PP * KS];   // gathered noisy neighbors
__device__ float  g_estim[BB * PP * KS * 3];
__device__ float  g_partial[BB * PP];

__device__ __forceinline__ float finf() { return __int_as_float(0x7f800000); }

// ---------------- K0: pack point clouds as float4 with |r|^2 ----------------
__global__ void k0_pack(const float* __restrict__ noisy, const float* __restrict__ clean) {
    int i = blockIdx.x * blockDim.x + threadIdx.x;
    if (i < BB * NN) {
        float x = noisy[i * 3 + 0], y = noisy[i * 3 + 1], z = noisy[i * 3 + 2];
        g_noisy4[i] = make_float4(x, y, z, fmaf(x, x, fmaf(y, y, z * z)));
    }
    if (i < BB * MM) {
        float x = clean[i * 3 + 0], y = clean[i * 3 + 1], z = clean[i * 3 + 2];
        g_clean4[i] = make_float4(x, y, z, fmaf(x, x, fmaf(y, y, z * z)));
    }
}

// ---------------- K1: f_origin, feat(sampled), zpart ----------------
__global__ void k1_feat(const float* __restrict__ noisy, const int* __restrict__ sidx,
                        const float* __restrict__ Wf1, const float* __restrict__ bf1,
                        const float* __restrict__ Wf2, const float* __restrict__ bf2,
                        const float* __restrict__ Ws1, const float* __restrict__ bs1) {
    int bp = blockIdx.x;            // 0..511
    int b = bp >> 7, p = bp & 127;
    int tid = threadIdx.x;          // 128 threads
    __shared__ float xyz[3];
    __shared__ float h[64];
    __shared__ float z[128];

    if (tid == 0) {
        int si = sidx[p];
        const float* s = noisy + ((size_t)b * NN + si) * 3;
        xyz[0] = s[0]; xyz[1] = s[1]; xyz[2] = s[2];
        g_forigin[bp] = make_float4(s[0], s[1], s[2], 0.f);
    }
    __syncthreads();

    if (tid < 64) {
        float a = bf1[tid];
        a = fmaf(xyz[0], Wf1[0 * 64 + tid], a);
        a = fmaf(xyz[1], Wf1[1 * 64 + tid], a);
        a = fmaf(xyz[2], Wf1[2 * 64 + tid], a);
        h[tid] = fmaxf(a, 0.f);
    }
    __syncthreads();

    {
        float a = bf2[tid];
#pragma unroll 16
        for (int i = 0; i < 64; ++i) a = fmaf(h[i], Wf2[i * 128 + tid], a);
        z[tid] = a;                 // feat: no relu on second layer
    }
    __syncthreads();

    {
        float a = bs1[tid];
#pragma unroll 16
        for (int i = 0; i < 128; ++i) a = fmaf(z[i], Ws1[(3 + i) * 128 + tid], a);
        g_zpart[bp * ZF + tid] = a;
    }
}

// ---------------- K2: KNN1 top-32 via threshold binary search ----------------
__global__ __launch_bounds__(256) void k2_knn1() {
    int bp = blockIdx.x;            // one query per block
    int b = bp >> 7;
    int tid = threadIdx.x;
    __shared__ unsigned keys[NN];   // 40 KB
    __shared__ unsigned s_cnt;

    float4 q = g_forigin[bp];
    float m2x = -2.0f * q.x, m2y = -2.0f * q.y, m2z = -2.0f * q.z;
    for (int r = tid; r < NN; r += 256) {
        float4 v = g_noisy4[b * NN + r];
        float s = fmaf(v.x, m2x, fmaf(v.y, m2y, fmaf(v.z, m2z, v.w))); // d2 - |q|^2
        unsigned u = __float_as_uint(s);
        u ^= ((unsigned)((int)u >> 31)) | 0x80000000u;  // monotone float->uint
        keys[r] = u;
    }
    __syncthreads();

    unsigned lo = 0u, hi = 0xFFFFFFFFu;
    for (int it = 0; it < 34 && lo + 1u < hi; ++it) {
        unsigned mid = lo + ((hi - lo) >> 1);
        if (tid == 0) s_cnt = 0;
        __syncthreads();
        unsigned c = 0;
        for (int r = tid; r < NN; r += 256) c += (keys[r] <= mid);
        c = __reduce_add_sync(0xFFFFFFFFu, c);
        if ((tid & 31) == 0) atomicAdd(&s_cnt, c);
        __syncthreads();
        unsigned cnt = s_cnt;
        __syncthreads();
        if (cnt >= 32u) { hi = mid; if (cnt == 32u) break; }
        else lo = mid;
    }
    unsigned T = hi;   // count(keys <= T) >= 32 (== 32 for distinct values)

    if (tid == 0) s_cnt = 0;
    __syncthreads();
    for (int r = tid; r < NN; r += 256) {
        if (keys[r] <= T) {
            unsigned pos = atomicAdd(&s_cnt, 1u);
            if (pos < 32u) g_fpts[bp * KS + pos] = g_noisy4[b * NN + r];
        }
    }
}

// ---------------- K3: score MLP — ONE WARP PER 4 ROWS ----------------
// 16384 rows / 4 = 4096 warps, 8 warps/block -> 512 blocks.
// Weights (Ws2) loaded once per warp serve 4 rows -> 4x fewer LDG wavefronts.
__global__ __launch_bounds__(256) void k3_mlp(const float* __restrict__ Ws1,
                                              const float* __restrict__ Ws2,
                                              const float* __restrict__ bs2,
                                              const float* __restrict__ Ws3,
                                              const float* __restrict__ bs3) {
    __shared__ float hsh[8][4][128];
    int w = threadIdx.x >> 5, lane = threadIdx.x & 31;
    int rbase = (blockIdx.x * 8 + w) * 4;   // rows rbase..rbase+3 share bp
    int bp = rbase >> 5;

    float4 o = g_forigin[bp];
    float X0[4], X1[4], X2[4];
#pragma unroll
    for (int j = 0; j < 4; ++j) {
        float4 f = g_fpts[rbase + j];       // warp-uniform address -> L1 broadcast
        X0[j] = f.x - o.x; X1[j] = f.y - o.y; X2[j] = f.z - o.z;
    }

    // layer 1: lane computes features 4*lane..4*lane+3 for each of 4 rows
    float4 zp = *(const float4*)(g_zpart + bp * ZF + lane * 4);
    float4 w0 = *(const float4*)(Ws1 + 0 * 128 + lane * 4);
    float4 w1 = *(const float4*)(Ws1 + 1 * 128 + lane * 4);
    float4 w2 = *(const float4*)(Ws1 + 2 * 128 + lane * 4);
#pragma unroll
    for (int j = 0; j < 4; ++j) {
        float4 h4;
        h4.x = fmaxf(fmaf(X2[j], w2.x, fmaf(X1[j], w1.x, fmaf(X0[j], w0.x, zp.x))), 0.f);
        h4.y = fmaxf(fmaf(X2[j], w2.y, fmaf(X1[j], w1.y, fmaf(X0[j], w0.y, zp.y))), 0.f);
        h4.z = fmaxf(fmaf(X2[j], w2.z, fmaf(X1[j], w1.z, fmaf(X0[j], w0.z, zp.z))), 0.f);
        h4.w = fmaxf(fmaf(X2[j], w2.w, fmaf(X1[j], w1.w, fmaf(X0[j], w0.w, zp.w))), 0.f);
        *(float4*)&hsh[w][j][lane * 4] = h4;
    }
    __syncwarp();

    // layer 2: lane owns output columns 2*lane, 2*lane+1; 4 rows at once
    float b20 = bs2[2 * lane], b21 = bs2[2 * lane + 1];
    float a0[4], a1[4];
#pragma unroll
    for (int j = 0; j < 4; ++j) { a0[j] = b20; a1[j] = b21; }
    const float2* __restrict__ W2 = (const float2*)(Ws2) + lane;  // (i, 2*lane)
#pragma unroll 8
    for (int i = 0; i < 128; i += 4) {
        float2 wv0 = W2[(i + 0) * 32];
        float2 wv1 = W2[(i + 1) * 32];
        float2 wv2 = W2[(i + 2) * 32];
        float2 wv3 = W2[(i + 3) * 32];
#pragma unroll
        for (int j = 0; j < 4; ++j) {
            float4 hv = *(const float4*)&hsh[w][j][i];   // broadcast LDS.128
            a0[j] = fmaf(hv.x, wv0.x, a0[j]); a1[j] = fmaf(hv.x, wv0.y, a1[j]);
            a0[j] = fmaf(hv.y, wv1.x, a0[j]); a1[j] = fmaf(hv.y, wv1.y, a1[j]);
            a0[j] = fmaf(hv.z, wv2.x, a0[j]); a1[j] = fmaf(hv.z, wv2.y, a1[j]);
            a0[j] = fmaf(hv.w, wv3.x, a0[j]); a1[j] = fmaf(hv.w, wv3.y, a1[j]);
        }
    }

    // layer 3: lane holds h2 cols 2*lane, 2*lane+1 -> rows 2l, 2l+1 of Ws3
    const float* __restrict__ w3 = Ws3 + 6 * lane;
    float w30 = w3[0], w31 = w3[1], w32 = w3[2];
    float w33 = w3[3], w34 = w3[4], w35 = w3[5];
    float ob0 = bs3[0], ob1 = bs3[1], ob2 = bs3[2];
#pragma unroll
    for (int j = 0; j < 4; ++j) {
        float h20 = fmaxf(a0[j], 0.f), h21 = fmaxf(a1[j], 0.f);
        float p0 = fmaf(h20, w30, h21 * w33);
        float p1 = fmaf(h20, w31, h21 * w34);
        float p2 = fmaf(h20, w32, h21 * w35);
#pragma unroll
        for (int off = 16; off > 0; off >>= 1) {
            p0 += __shfl_xor_sync(0xFFFFFFFFu, p0, off);
            p1 += __shfl_xor_sync(0xFFFFFFFFu, p1, off);
            p2 += __shfl_xor_sync(0xFFFFFFFFu, p2, off);
        }
        if (lane == 0) {
            g_estim[(rbase + j) * 3 + 0] = p0 + ob0;
            g_estim[(rbase + j) * 3 + 1] = p1 + ob1;
            g_estim[(rbase + j) * 3 + 2] = p2 + ob2;
        }
    }
}

// insertion into sorted 4-element top list
#define INS4(s, id, s0, s1, s2, s3, i0, i1, i2, i3)             \
    if ((s) < (s3)) {                                           \
        if ((s) < (s2)) {                                       \
            (s3) = (s2); (i3) = (i2);                           \
            if ((s) < (s1)) {                                   \
                (s2) = (s1); (i2) = (i1);                       \
                if ((s) < (s0)) { (s1) = (s0); (i1) = (i0); (s0) = (s); (i0) = (id); } \
                else { (s1) = (s); (i1) = (id); }               \
            } else { (s2) = (s); (i2) = (id); }                 \
        } else { (s3) = (s); (i3) = (id); }                     \
    }

// ---------------- K4: KNN2 top-4 + ground score + loss partials ----------------
__global__ __launch_bounds__(256) void k4_knn2() {
    int bp = blockIdx.x;
    int b = bp >> 7;
    int tid = threadIdx.x, lane = tid & 31, w = tid >> 5;   // 8 warps
    __shared__ float4 buf[2048];                 // 32 KB tile
    __shared__ float  cs[8][32][4];
    __shared__ int    ci[8][32][4];

    float4 f = g_fpts[bp * KS + lane];           // lane = query k
    float m2x = -2.0f * f.x, m2y = -2.0f * f.y, m2z = -2.0f * f.z;
    float s0 = finf(), s1 = finf(), s2 = finf(), s3 = finf();
    int   i0 = 0, i1 = 0, i2 = 0, i3 = 0;

    for (int t0 = 0; t0 < MM; t0 += 2048) {
        int n = min(2048, MM - t0);
        __syncthreads();
        for (int j = tid; j < n; j += 256) buf[j] = g_clean4[b * MM + t0 + j];
        __syncthreads();
        int chunk = (n + 7) >> 3;
        int start = w * chunk;
        int end = min(start + chunk, n);
#pragma unroll 4
        for (int r = start; r < end; ++r) {
            float4 v = buf[r];                   // broadcast LDS.128
            float s = fmaf(v.x, m2x, fmaf(v.y, m2y, fmaf(v.z, m2z, v.w)));
            int id = t0 + r;
            INS4(s, id, s0, s1, s2, s3, i0, i1, i2, i3);
        }
    }
    cs[w][lane][0] = s0; cs[w][lane][1] = s1; cs[w][lane][2] = s2; cs[w][lane][3] = s3;
    ci[w][lane][0] = i0; ci[w][lane][1] = i1; ci[w][lane][2] = i2; ci[w][lane][3] = i3;
    __syncthreads();

    if (w == 0) {
        float b0 = finf(), b1 = finf(), b2 = finf(), b3 = finf();
        int   j0 = 0, j1 = 0, j2 = 0, j3 = 0;
#pragma unroll
        for (int ww = 0; ww < 8; ++ww)
#pragma unroll
            for (int jj = 0; jj < 4; ++jj) {
                float s = cs[ww][lane][jj];
                int id = ci[ww][lane][jj];
                INS4(s, id, b0, b1, b2, b3, j0, j1, j2, j3);
            }
        float4 c0 = g_clean4[b * MM + j0];
        float4 c1 = g_clean4[b * MM + j1];
        float4 c2 = g_clean4[b * MM + j2];
        float4 c3 = g_clean4[b * MM + j3];
        float gx = (c0.x + c1.x + c2.x + c3.x) * 0.25f - f.x;
        float gy = (c0.y + c1.y + c2.y + c3.y) * 0.25f - f.y;
        float gz = (c0.z + c1.z + c2.z + c3.z) * 0.25f - f.z;
        const float* e = g_estim + (bp * KS + lane) * 3;
        float d0 = e[0] - gx, d1 = e[1] - gy, d2v = e[2] - gz;
        float err = fmaf(d0, d0, fmaf(d1, d1, d2v * d2v));
#pragma unroll
        for (int off = 16; off > 0; off >>= 1)
            err += __shfl_xor_sync(0xFFFFFFFFu, err, off);
        if (lane == 0) g_partial[bp] = err;
    }
}

// ---------------- K5: deterministic final reduce ----------------
__global__ void k5_reduce(float* __restrict__ out) {
    __shared__ float sm[512];
    int tid = threadIdx.x;
    sm[tid] = g_partial[tid];
    __syncthreads();
#pragma unroll
    for (int s = 256; s > 0; s >>= 1) {
        if (tid < s) sm[tid] += sm[tid + s];
        __syncthreads();
    }
    // loss = 0.5 * mean_{B*P*K}( sum_d (.)^2 / SIGMA ) = total * 0.5*100/16384
    if (tid == 0) out[0] = sm[0] * (50.0f / 16384.0f);
}

extern "C" void kernel_launch(void* const* d_in, const int* in_sizes, int n_in,
                              void* d_out, int out_size) {
    const float* noisy = (const float*)d_in[0];
    const float* clean = (const float*)d_in[1];
    const int*   sidx  = (const int*)d_in[2];
    const float* Wf1 = (const float*)d_in[3];
    const float* bf1 = (const float*)d_in[4];
    const float* Wf2 = (const float*)d_in[5];
    const float* bf2 = (const float*)d_in[6];
    const float* Ws1 = (const float*)d_in[7];
    const float* bs1 = (const float*)d_in[8];
    const float* Ws2 = (const float*)d_in[9];
    const float* bs2 = (const float*)d_in[10];
    const float* Ws3 = (const float*)d_in[11];
    const float* bs3 = (const float*)d_in[12];
    float* out = (float*)d_out;

    k0_pack<<<(BB * NN + 255) / 256, 256>>>(noisy, clean);
    k1_feat<<<BB * PP, 128>>>(noisy, sidx, Wf1, bf1, Wf2, bf2, Ws1, bs1);
    k2_knn1<<<BB * PP, 256>>>();
    k3_mlp<<<BB * PP * KS / 32, 256>>>(Ws1, Ws2, bs2, Ws3, bs3);
    k4_knn2<<<BB * PP, 256>>>();
    k5_reduce<<<1, 512>>>(out);
}

// round 6
// speedup vs baseline: 1.5404x; 1.2531x over previous
#include <cuda_runtime.h>
#include <cuda_bf16.h>

#define BB 4
#define NN 10000
#define MM 10000
#define PP 128
#define KS 32
#define ZF 128

// ---------------- device scratch (static: no allocation) ----------------
__device__ float4 g_noisy4[BB * NN];      // (x,y,z, x^2+y^2+z^2)
__device__ float4 g_clean4[BB * MM];
__device__ float4 g_forigin[BB * PP];
__device__ float  g_zpart[BB * PP * ZF];  // Ws1[3:]^T z + bs1 per (b,p)
__device__ float4 g_fpts[BB * PP * KS];   // gathered noisy neighbors
__device__ float  g_estim[BB * PP * KS * 3];
__device__ float  g_partial[BB * PP];

__device__ __forceinline__ float finf() { return __int_as_float(0x7f800000); }

// ---------------- K0: pack point clouds as float4 with |r|^2 ----------------
__global__ void k0_pack(const float* __restrict__ noisy, const float* __restrict__ clean) {
    int i = blockIdx.x * blockDim.x + threadIdx.x;
    if (i < BB * NN) {
        float x = noisy[i * 3 + 0], y = noisy[i * 3 + 1], z = noisy[i * 3 + 2];
        g_noisy4[i] = make_float4(x, y, z, fmaf(x, x, fmaf(y, y, z * z)));
    }
    if (i < BB * MM) {
        float x = clean[i * 3 + 0], y = clean[i * 3 + 1], z = clean[i * 3 + 2];
        g_clean4[i] = make_float4(x, y, z, fmaf(x, x, fmaf(y, y, z * z)));
    }
}

// ---------------- K1: f_origin, feat(sampled), zpart ----------------
__global__ void k1_feat(const float* __restrict__ noisy, const int* __restrict__ sidx,
                        const float* __restrict__ Wf1, const float* __restrict__ bf1,
                        const float* __restrict__ Wf2, const float* __restrict__ bf2,
                        const float* __restrict__ Ws1, const float* __restrict__ bs1) {
    int bp = blockIdx.x;            // 0..511
    int b = bp >> 7, p = bp & 127;
    int tid = threadIdx.x;          // 128 threads
    __shared__ float xyz[3];
    __shared__ float h[64];
    __shared__ float z[128];

    if (tid == 0) {
        int si = sidx[p];
        const float* s = noisy + ((size_t)b * NN + si) * 3;
        xyz[0] = s[0]; xyz[1] = s[1]; xyz[2] = s[2];
        g_forigin[bp] = make_float4(s[0], s[1], s[2], 0.f);
    }
    __syncthreads();

    if (tid < 64) {
        float a = bf1[tid];
        a = fmaf(xyz[0], Wf1[0 * 64 + tid], a);
        a = fmaf(xyz[1], Wf1[1 * 64 + tid], a);
        a = fmaf(xyz[2], Wf1[2 * 64 + tid], a);
        h[tid] = fmaxf(a, 0.f);
    }
    __syncthreads();

    {
        float a = bf2[tid];
#pragma unroll 16
        for (int i = 0; i < 64; ++i) a = fmaf(h[i], Wf2[i * 128 + tid], a);
        z[tid] = a;                 // feat: no relu on second layer
    }
    __syncthreads();

    {
        float a = bs1[tid];
#pragma unroll 16
        for (int i = 0; i < 128; ++i) a = fmaf(z[i], Ws1[(3 + i) * 128 + tid], a);
        g_zpart[bp * ZF + tid] = a;
    }
}

// ---------------- K2: KNN1 top-32 via 4-level radix select ----------------
__global__ __launch_bounds__(256) void k2_knn1() {
    int bp = blockIdx.x;            // one query per block
    int b = bp >> 7;
    int tid = threadIdx.x, lane = tid & 31;
    __shared__ unsigned keys[NN];   // 40 KB
    __shared__ unsigned hist[257];  // 256 bins + 1 dummy
    __shared__ unsigned s_prefix, s_want, s_cnt;

    float4 q = g_forigin[bp];
    float m2x = -2.0f * q.x, m2y = -2.0f * q.y, m2z = -2.0f * q.z;
    for (int r = tid; r < NN; r += 256) {
        float4 v = g_noisy4[b * NN + r];
        float s = fmaf(v.x, m2x, fmaf(v.y, m2y, fmaf(v.z, m2z, v.w))); // d2 - |q|^2
        unsigned u = __float_as_uint(s);
        u ^= ((unsigned)((int)u >> 31)) | 0x80000000u;  // monotone float->uint
        keys[r] = u;
    }

    unsigned prefix = 0u, want = 32u;
#pragma unroll
    for (int level = 0; level < 4; ++level) {
        const int shift = 24 - 8 * level;
        const unsigned mask = (level == 0) ? 0u : (0xFFFFFFFFu << (shift + 8));
        hist[tid] = 0u;
        if (tid == 0) hist[256] = 0u;
        __syncthreads();             // keys + hist visible
        for (int r = tid; r < NN; r += 256) {
            unsigned k = keys[r];
            bool match = ((k ^ prefix) & mask) == 0u;
            unsigned bin = (k >> shift) & 0xFFu;
            atomicAdd(&hist[match ? bin : 256u], 1u);   // branchless (dummy bin)
        }
        __syncthreads();
        if (tid < 32) {
            // lane covers bins 8*lane .. 8*lane+7
            unsigned c[8], lsum = 0u;
#pragma unroll
            for (int j = 0; j < 8; ++j) { c[j] = hist[8 * lane + j]; lsum += c[j]; }
            unsigned incl = lsum;
#pragma unroll
            for (int off = 1; off < 32; off <<= 1) {
                unsigned t = __shfl_up_sync(0xFFFFFFFFu, incl, off);
                if (lane >= off) incl += t;
            }
            unsigned excl = incl - lsum;
            if (excl < want && want <= incl) {          // exactly one lane
                unsigned acc = excl;
#pragma unroll
                for (int j = 0; j < 8; ++j) {
                    if (want <= acc + c[j]) {
                        s_prefix = prefix | ((unsigned)(8 * lane + j) << shift);
                        s_want = want - acc;
                        break;
                    }
                    acc += c[j];
                }
            }
        }
        __syncthreads();
        prefix = s_prefix; want = s_want;
        __syncthreads();            // protect s_prefix before next level reuse
    }
    unsigned T = prefix;            // exact 32nd-smallest key

    if (tid == 0) s_cnt = 0u;
    __syncthreads();
    for (int r = tid; r < NN; r += 256) {
        if (keys[r] <= T) {
            unsigned pos = atomicAdd(&s_cnt, 1u);
            if (pos < 32u) g_fpts[bp * KS + pos] = g_noisy4[b * NN + r];
        }
    }
}

// ---------------- K3: score MLP — ONE WARP PER 4 ROWS ----------------
__global__ __launch_bounds__(256) void k3_mlp(const float* __restrict__ Ws1,
                                              const float* __restrict__ Ws2,
                                              const float* __restrict__ bs2,
                                              const float* __restrict__ Ws3,
                                              const float* __restrict__ bs3) {
    __shared__ float hsh[8][4][128];
    int w = threadIdx.x >> 5, lane = threadIdx.x & 31;
    int rbase = (blockIdx.x * 8 + w) * 4;   // rows rbase..rbase+3 share bp
    int bp = rbase >> 5;

    float4 o = g_forigin[bp];
    float X0[4], X1[4], X2[4];
#pragma unroll
    for (int j = 0; j < 4; ++j) {
        float4 f = g_fpts[rbase + j];       // warp-uniform address -> L1 broadcast
        X0[j] = f.x - o.x; X1[j] = f.y - o.y; X2[j] = f.z - o.z;
    }

    float4 zp = *(const float4*)(g_zpart + bp * ZF + lane * 4);
    float4 w0 = *(const float4*)(Ws1 + 0 * 128 + lane * 4);
    float4 w1 = *(const float4*)(Ws1 + 1 * 128 + lane * 4);
    float4 w2 = *(const float4*)(Ws1 + 2 * 128 + lane * 4);
#pragma unroll
    for (int j = 0; j < 4; ++j) {
        float4 h4;
        h4.x = fmaxf(fmaf(X2[j], w2.x, fmaf(X1[j], w1.x, fmaf(X0[j], w0.x, zp.x))), 0.f);
        h4.y = fmaxf(fmaf(X2[j], w2.y, fmaf(X1[j], w1.y, fmaf(X0[j], w0.y, zp.y))), 0.f);
        h4.z = fmaxf(fmaf(X2[j], w2.z, fmaf(X1[j], w1.z, fmaf(X0[j], w0.z, zp.z))), 0.f);
        h4.w = fmaxf(fmaf(X2[j], w2.w, fmaf(X1[j], w1.w, fmaf(X0[j], w0.w, zp.w))), 0.f);
        *(float4*)&hsh[w][j][lane * 4] = h4;
    }
    __syncwarp();

    float b20 = bs2[2 * lane], b21 = bs2[2 * lane + 1];
    float a0[4], a1[4];
#pragma unroll
    for (int j = 0; j < 4; ++j) { a0[j] = b20; a1[j] = b21; }
    const float2* __restrict__ W2 = (const float2*)(Ws2) + lane;  // (i, 2*lane)
#pragma unroll 8
    for (int i = 0; i < 128; i += 4) {
        float2 wv0 = W2[(i + 0) * 32];
        float2 wv1 = W2[(i + 1) * 32];
        float2 wv2 = W2[(i + 2) * 32];
        float2 wv3 = W2[(i + 3) * 32];
#pragma unroll
        for (int j = 0; j < 4; ++j) {
            float4 hv = *(const float4*)&hsh[w][j][i];   // broadcast LDS.128
            a0[j] = fmaf(hv.x, wv0.x, a0[j]); a1[j] = fmaf(hv.x, wv0.y, a1[j]);
            a0[j] = fmaf(hv.y, wv1.x, a0[j]); a1[j] = fmaf(hv.y, wv1.y, a1[j]);
            a0[j] = fmaf(hv.z, wv2.x, a0[j]); a1[j] = fmaf(hv.z, wv2.y, a1[j]);
            a0[j] = fmaf(hv.w, wv3.x, a0[j]); a1[j] = fmaf(hv.w, wv3.y, a1[j]);
        }
    }

    const float* __restrict__ w3 = Ws3 + 6 * lane;
    float w30 = w3[0], w31 = w3[1], w32 = w3[2];
    float w33 = w3[3], w34 = w3[4], w35 = w3[5];
    float ob0 = bs3[0], ob1 = bs3[1], ob2 = bs3[2];
#pragma unroll
    for (int j = 0; j < 4; ++j) {
        float h20 = fmaxf(a0[j], 0.f), h21 = fmaxf(a1[j], 0.f);
        float p0 = fmaf(h20, w30, h21 * w33);
        float p1 = fmaf(h20, w31, h21 * w34);
        float p2 = fmaf(h20, w32, h21 * w35);
#pragma unroll
        for (int off = 16; off > 0; off >>= 1) {
            p0 += __shfl_xor_sync(0xFFFFFFFFu, p0, off);
            p1 += __shfl_xor_sync(0xFFFFFFFFu, p1, off);
            p2 += __shfl_xor_sync(0xFFFFFFFFu, p2, off);
        }
        if (lane == 0) {
            g_estim[(rbase + j) * 3 + 0] = p0 + ob0;
            g_estim[(rbase + j) * 3 + 1] = p1 + ob1;
            g_estim[(rbase + j) * 3 + 2] = p2 + ob2;
        }
    }
}

// insertion into sorted 4-element top list
#define INS4(s, id, s0, s1, s2, s3, i0, i1, i2, i3)             \
    if ((s) < (s3)) {                                           \
        if ((s) < (s2)) {                                       \
            (s3) = (s2); (i3) = (i2);                           \
            if ((s) < (s1)) {                                   \
                (s2) = (s1); (i2) = (i1);                       \
                if ((s) < (s0)) { (s1) = (s0); (i1) = (i0); (s0) = (s); (i0) = (id); } \
                else { (s1) = (s); (i1) = (id); }               \
            } else { (s2) = (s); (i2) = (id); }                 \
        } else { (s3) = (s); (i3) = (id); }                     \
    }

// ---------------- K4: KNN2 top-4, grouped compare (1 branch per 4 refs) -------
__global__ __launch_bounds__(256) void k4_knn2() {
    int bp = blockIdx.x;
    int b = bp >> 7;
    int tid = threadIdx.x, lane = tid & 31, w = tid >> 5;   // 8 warps
    __shared__ float4 buf[2048];                 // 32 KB tile
    __shared__ float  cs[8][32][4];
    __shared__ int    ci[8][32][4];

    float4 f = g_fpts[bp * KS + lane];           // lane = query k
    float m2x = -2.0f * f.x, m2y = -2.0f * f.y, m2z = -2.0f * f.z;
    float s0 = finf(), s1 = finf(), s2 = finf(), s3 = finf();
    int   i0 = 0, i1 = 0, i2 = 0, i3 = 0;

    for (int t0 = 0; t0 < MM; t0 += 2048) {
        int n = min(2048, MM - t0);
        __syncthreads();
        for (int j = tid; j < n; j += 256) buf[j] = g_clean4[b * MM + t0 + j];
        __syncthreads();
        int chunk = (n + 7) >> 3;
        int start = w * chunk;
        int end = min(start + chunk, n);
        int r = start;
#pragma unroll 2
        for (; r + 4 <= end; r += 4) {
            float4 v0 = buf[r + 0];
            float4 v1 = buf[r + 1];
            float4 v2 = buf[r + 2];
            float4 v3 = buf[r + 3];
            float sa = fmaf(v0.x, m2x, fmaf(v0.y, m2y, fmaf(v0.z, m2z, v0.w)));
            float sb = fmaf(v1.x, m2x, fmaf(v1.y, m2y, fmaf(v1.z, m2z, v1.w)));
            float sc = fmaf(v2.x, m2x, fmaf(v2.y, m2y, fmaf(v2.z, m2z, v2.w)));
            float sd = fmaf(v3.x, m2x, fmaf(v3.y, m2y, fmaf(v3.z, m2z, v3.w)));
            float m = fminf(fminf(sa, sb), fminf(sc, sd));
            if (m < s3) {                        // rare: ~30x per 10000
                INS4(sa, t0 + r + 0, s0, s1, s2, s3, i0, i1, i2, i3);
                INS4(sb, t0 + r + 1, s0, s1, s2, s3, i0, i1, i2, i3);
                INS4(sc, t0 + r + 2, s0, s1, s2, s3, i0, i1, i2, i3);
                INS4(sd, t0 + r + 3, s0, s1, s2, s3, i0, i1, i2, i3);
            }
        }
        for (; r < end; ++r) {
            float4 v = buf[r];
            float s = fmaf(v.x, m2x, fmaf(v.y, m2y, fmaf(v.z, m2z, v.w)));
            int id = t0 + r;
            INS4(s, id, s0, s1, s2, s3, i0, i1, i2, i3);
        }
    }
    cs[w][lane][0] = s0; cs[w][lane][1] = s1; cs[w][lane][2] = s2; cs[w][lane][3] = s3;
    ci[w][lane][0] = i0; ci[w][lane][1] = i1; ci[w][lane][2] = i2; ci[w][lane][3] = i3;
    __syncthreads();

    if (w == 0) {
        float b0 = finf(), b1 = finf(), b2 = finf(), b3 = finf();
        int   j0 = 0, j1 = 0, j2 = 0, j3 = 0;
#pragma unroll
        for (int ww = 0; ww < 8; ++ww)
#pragma unroll
            for (int jj = 0; jj < 4; ++jj) {
                float s = cs[ww][lane][jj];
                int id = ci[ww][lane][jj];
                INS4(s, id, b0, b1, b2, b3, j0, j1, j2, j3);
            }
        float4 c0 = g_clean4[b * MM + j0];
        float4 c1 = g_clean4[b * MM + j1];
        float4 c2 = g_clean4[b * MM + j2];
        float4 c3 = g_clean4[b * MM + j3];
        float gx = (c0.x + c1.x + c2.x + c3.x) * 0.25f - f.x;
        float gy = (c0.y + c1.y + c2.y + c3.y) * 0.25f - f.y;
        float gz = (c0.z + c1.z + c2.z + c3.z) * 0.25f - f.z;
        const float* e = g_estim + (bp * KS + lane) * 3;
        float d0 = e[0] - gx, d1 = e[1] - gy, d2v = e[2] - gz;
        float err = fmaf(d0, d0, fmaf(d1, d1, d2v * d2v));
#pragma unroll
        for (int off = 16; off > 0; off >>= 1)
            err += __shfl_xor_sync(0xFFFFFFFFu, err, off);
        if (lane == 0) g_partial[bp] = err;
    }
}

// ---------------- K5: deterministic final reduce ----------------
__global__ void k5_reduce(float* __restrict__ out) {
    __shared__ float sm[512];
    int tid = threadIdx.x;
    sm[tid] = g_partial[tid];
    __syncthreads();
#pragma unroll
    for (int s = 256; s > 0; s >>= 1) {
        if (tid < s) sm[tid] += sm[tid + s];
        __syncthreads();
    }
    // loss = 0.5 * mean_{B*P*K}( sum_d (.)^2 / SIGMA ) = total * 0.5*100/16384
    if (tid == 0) out[0] = sm[0] * (50.0f / 16384.0f);
}

extern "C" void kernel_launch(void* const* d_in, const int* in_sizes, int n_in,
                              void* d_out, int out_size) {
    const float* noisy = (const float*)d_in[0];
    const float* clean = (const float*)d_in[1];
    const int*   sidx  = (const int*)d_in[2];
    const float* Wf1 = (const float*)d_in[3];
    const float* bf1 = (const float*)d_in[4];
    const float* Wf2 = (const float*)d_in[5];
    const float* bf2 = (const float*)d_in[6];
    const float* Ws1 = (const float*)d_in[7];
    const float* bs1 = (const float*)d_in[8];
    const float* Ws2 = (const float*)d_in[9];
    const float* bs2 = (const float*)d_in[10];
    const float* Ws3 = (const float*)d_in[11];
    const float* bs3 = (const float*)d_in[12];
    float* out = (float*)d_out;

    k0_pack<<<(BB * NN + 255) / 256, 256>>>(noisy, clean);
    k1_feat<<<BB * PP, 128>>>(noisy, sidx, Wf1, bf1, Wf2, bf2, Ws1, bs1);
    k2_knn1<<<BB * PP, 256>>>();
    k3_mlp<<<BB * PP * KS / 32, 256>>>(Ws1, Ws2, bs2, Ws3, bs3);
    k4_knn2<<<BB * PP, 256>>>();
    k5_reduce<<<1, 512>>>(out);
}